// round 13
// baseline (speedup 1.0000x reference)
#include <cuda_runtime.h>
#include <cuda_bf16.h>
#include <cstdint>
#include <cstring>

#define TS   512
#define BSZ  256
#define DIN  256
#define HID  256
#define OUTD 64
#define MROWS (TS * BSZ)
#define NCTA_S 128           // serial: 8 row-groups x 16 col-CTAs
#define PAK  40              // staged tile pitch in bf16 (80B rows: ldmatrix conflict-free)

// xw_mma smem layout (bytes)
#define OFF_BIAS 0
#define OFF_AH   1024
#define OFF_AL   (OFF_AH + 128 * PAK * 2)
#define OFF_BH   (OFF_AL + 128 * PAK * 2)
#define OFF_BL   (OFF_BH + 128 * PAK * 2)
#define SMEM_MMA (OFF_BL + 128 * PAK * 2)      // 41984 B

// serial smem layout (bytes): A 32rx256k hi/lo, W 64nx256k hi/lo, pitch 80B, 8 k-chunks
#define S_AH  0
#define S_AL  20480            // 8 * 32*80
#define S_WH  40960
#define S_WL  (S_WH + 40960)
#define SMEM_SER (S_WL + 40960)   // 122880 B

extern __shared__ char smem_dyn[];

__device__ float          g_xwb[(size_t)MROWS * 1024];   // x@Wx + b, [m][g*256+j]
__device__ __nv_bfloat16  g_ah[(size_t)MROWS * DIN];
__device__ __nv_bfloat16  g_al[(size_t)MROWS * DIN];
__device__ __nv_bfloat16  g_wth[1024 * 256];              // W^T hi [n][k]
__device__ __nv_bfloat16  g_wtl[1024 * 256];              // W^T lo
__device__ uint32_t       g_hpk[2][BSZ * HID];            // h packed: hi bf16 <<16 | lo bf16
__device__ __align__(64) unsigned g_slots[8][16];         // per-group slot barrier (one 64B line)
__device__ unsigned       g_bar;                          // final global barrier

__device__ __forceinline__ float sigmoidf_(float x) { return 1.0f / (1.0f + __expf(-x)); }
__device__ __forceinline__ float tanhf_(float x) {
    float e = __expf(2.0f * x); return 1.0f - 2.0f / (e + 1.0f);
}
__device__ __forceinline__ uint32_t s2u(const void* p) {
    uint32_t a; asm("{ .reg .u64 t; cvta.to.shared.u64 t, %1; cvt.u32.u64 %0, t; }" : "=r"(a) : "l"(p));
    return a;
}
__device__ __forceinline__ uint32_t pack2(float a, float b) {
    __nv_bfloat162 t; t.x = __float2bfloat16(a); t.y = __float2bfloat16(b);
    uint32_t r; memcpy(&r, &t, 4); return r;
}
__device__ __forceinline__ float rebf(float v) {
    return __bfloat162float(__float2bfloat16(v));
}
__device__ __forceinline__ uint32_t packsplit(float v) {
    __nv_bfloat16 hb = __float2bfloat16(v);
    unsigned short hu; memcpy(&hu, &hb, 2);
    float hf = __uint_as_float((uint32_t)hu << 16);
    __nv_bfloat16 lb = __float2bfloat16(v - hf);
    unsigned short lu; memcpy(&lu, &lb, 2);
    return ((uint32_t)hu << 16) | (uint32_t)lu;
}
__device__ __forceinline__ float unpacksplit(uint32_t u) {
    return __uint_as_float(u & 0xFFFF0000u) + __uint_as_float(u << 16);
}
__device__ __forceinline__ void arrive_release(unsigned* ctr) {
    asm volatile("red.release.gpu.global.add.u32 [%0], %1;" :: "l"(ctr), "r"(1u) : "memory");
}
__device__ __forceinline__ void wait_target(const unsigned* ctr, unsigned tgt) {
    unsigned v;
    do {
        asm volatile("ld.global.acquire.gpu.u32 %0, [%1];" : "=r"(v) : "l"(ctr));
        if (v >= tgt) break;
        __nanosleep(20);
    } while (true);
}

#define LDSM4(d0, d1, d2, d3, addr) \
    asm volatile("ldmatrix.sync.aligned.m8n8.x4.shared.b16 {%0,%1,%2,%3}, [%4];" \
                 : "=r"(d0), "=r"(d1), "=r"(d2), "=r"(d3) : "r"(addr))

#define MMA16816(c, a, b0, b1) \
    asm volatile("mma.sync.aligned.m16n8k16.row.col.f32.bf16.bf16.f32 " \
                 "{%0,%1,%2,%3}, {%4,%5,%6,%7}, {%8,%9}, {%0,%1,%2,%3};" \
                 : "+f"((c)[0]), "+f"((c)[1]), "+f"((c)[2]), "+f"((c)[3]) \
                 : "r"((a)[0]), "r"((a)[1]), "r"((a)[2]), "r"((a)[3]), "r"(b0), "r"(b1))

// ---------------- conversions ----------------
__global__ void convert_x(const float* __restrict__ x) {
    size_t i = (size_t)blockIdx.x * 256 + threadIdx.x;
    float4 v = ((const float4*)x)[i];
    uint2 ph, pl;
    ph.x = pack2(v.x, v.y); ph.y = pack2(v.z, v.w);
    pl.x = pack2(v.x - rebf(v.x), v.y - rebf(v.y));
    pl.y = pack2(v.z - rebf(v.z), v.w - rebf(v.w));
    ((uint2*)g_ah)[i] = ph;
    ((uint2*)g_al)[i] = pl;
}

__global__ void convert_w(const float* __restrict__ Wf, const float* __restrict__ Wi,
                          const float* __restrict__ Wc, const float* __restrict__ Wo) {
    int n = blockIdx.x, k = threadIdx.x;
    int g = n >> 8, j = n & 255;
    const float* Wg = (g == 0) ? Wf : (g == 1) ? Wi : (g == 2) ? Wc : Wo;
    float v = Wg[(size_t)k * HID + j];
    g_wth[n * 256 + k] = __float2bfloat16(v);
    g_wtl[n * 256 + k] = __float2bfloat16(v - rebf(v));
}

// ---------------- xwb = x @ Wx + b via mma.sync bf16 3-term split ----------------
__global__ void __launch_bounds__(256) xw_mma(
    const float* __restrict__ bfp, const float* __restrict__ bip,
    const float* __restrict__ bcp, const float* __restrict__ bop)
{
    char* sm = smem_dyn;
    float* sBias = (float*)(sm + OFF_BIAS);
    const uint32_t uAh = s2u(sm + OFF_AH);
    const uint32_t uAl = s2u(sm + OFF_AL);
    const uint32_t uBh = s2u(sm + OFF_BH);
    const uint32_t uBl = s2u(sm + OFF_BL);

    const int tid  = threadIdx.x;
    const int w    = tid >> 5;
    const int lane = tid & 31;
    const int wm   = w & 3;
    const int wn   = w >> 2;
    const int n0   = blockIdx.x * 128;
    const int m0   = blockIdx.y * 128;

    if (tid < 128) {
        int g = n0 >> 8;
        const float* bg = (g == 0) ? bfp : (g == 1) ? bip : (g == 2) ? bcp : bop;
        sBias[tid] = bg[(n0 & 255) + tid];
    }

    const int arow  = lane & 15;
    const int ahalf = (lane >> 4) & 1;
    const int brow  = ((lane >> 4) & 1) * 8 + (lane & 7);
    const int bcol  = ((lane >> 3) & 1) * 8;

    float c[2][8][4];
    #pragma unroll
    for (int mt = 0; mt < 2; ++mt)
        #pragma unroll
        for (int nt = 0; nt < 8; ++nt)
            #pragma unroll
            for (int q = 0; q < 4; ++q) c[mt][nt][q] = 0.f;

    for (int ck = 0; ck < 8; ++ck) {
        const int k0 = ck * 32;
        __syncthreads();
        #pragma unroll
        for (int it = 0; it < 2; ++it) {
            int idx = tid + it * 256;
            int r = idx >> 2, cq = idx & 3;
            uint32_t doff = (uint32_t)(r * (PAK * 2) + cq * 16);
            *(uint4*)(sm + OFF_AH + doff) = *(const uint4*)(g_ah  + (size_t)(m0 + r) * 256 + k0 + cq * 8);
            *(uint4*)(sm + OFF_AL + doff) = *(const uint4*)(g_al  + (size_t)(m0 + r) * 256 + k0 + cq * 8);
            *(uint4*)(sm + OFF_BH + doff) = *(const uint4*)(g_wth + (size_t)(n0 + r) * 256 + k0 + cq * 8);
            *(uint4*)(sm + OFF_BL + doff) = *(const uint4*)(g_wtl + (size_t)(n0 + r) * 256 + k0 + cq * 8);
        }
        __syncthreads();

        #pragma unroll
        for (int ks = 0; ks < 2; ++ks) {
            const int kk = ks * 16;
            uint32_t ah[2][4], al[2][4];
            #pragma unroll
            for (int mt = 0; mt < 2; ++mt) {
                uint32_t ao = (uint32_t)((wm * 32 + mt * 16 + arow) * (PAK * 2) + (kk + ahalf * 8) * 2);
                LDSM4(ah[mt][0], ah[mt][1], ah[mt][2], ah[mt][3], uAh + ao);
                LDSM4(al[mt][0], al[mt][1], al[mt][2], al[mt][3], uAl + ao);
            }
            #pragma unroll
            for (int np = 0; np < 4; ++np) {
                uint32_t bo = (uint32_t)((wn * 64 + np * 16 + brow) * (PAK * 2) + (kk + bcol) * 2);
                uint32_t bh[4], bl[4];
                LDSM4(bh[0], bh[1], bh[2], bh[3], uBh + bo);
                LDSM4(bl[0], bl[1], bl[2], bl[3], uBl + bo);
                #pragma unroll
                for (int mt = 0; mt < 2; ++mt) {
                    MMA16816(c[mt][2 * np],     ah[mt], bh[0], bh[1]);
                    MMA16816(c[mt][2 * np + 1], ah[mt], bh[2], bh[3]);
                    MMA16816(c[mt][2 * np],     ah[mt], bl[0], bl[1]);
                    MMA16816(c[mt][2 * np + 1], ah[mt], bl[2], bl[3]);
                    MMA16816(c[mt][2 * np],     al[mt], bh[0], bh[1]);
                    MMA16816(c[mt][2 * np + 1], al[mt], bh[2], bh[3]);
                }
            }
        }
    }

    const int g  = lane >> 2;
    const int tg = lane & 3;
    float* base = g_xwb + (size_t)(m0 + wm * 32) * 1024 + n0 + wn * 64;
    #pragma unroll
    for (int mt = 0; mt < 2; ++mt) {
        #pragma unroll
        for (int nt = 0; nt < 8; ++nt) {
            float2 bv = *(float2*)&sBias[wn * 64 + nt * 8 + 2 * tg];
            float2 v0, v1;
            v0.x = c[mt][nt][0] + bv.x; v0.y = c[mt][nt][1] + bv.y;
            v1.x = c[mt][nt][2] + bv.x; v1.y = c[mt][nt][3] + bv.y;
            *(float2*)(base + (size_t)(mt * 16 + g)     * 1024 + nt * 8 + 2 * tg) = v0;
            *(float2*)(base + (size_t)(mt * 16 + g + 8) * 1024 + nt * 8 + 2 * tg) = v1;
        }
    }
}

// ---------------- init ----------------
__global__ void init_state() {
    int i = blockIdx.x * blockDim.x + threadIdx.x;
    if (i == 0) g_bar = 0u;
    if (i < 8 * 16) ((unsigned*)g_slots)[i] = 0u;
    if (i < BSZ * HID / 4) ((uint4*)g_hpk[0])[i] = make_uint4(0u, 0u, 0u, 0u);
}

// ---------------- serial loop: h @ Wh via mma.sync, warp-local epilogue ----------------
// 128 CTAs = 8 row-groups(32 rows) x 16 col-CTAs(16 hcols).
// Slot barrier: each CTA st.release's step number into its own word of the
// group's 64B line; every warp polls all 16 slots (no atomics, no tail sync).
__global__ void __launch_bounds__(256, 1) lstm_serial(
    const int* __restrict__ lengths,
    const float* __restrict__ Wf, const float* __restrict__ Wi,
    const float* __restrict__ Wc, const float* __restrict__ Wo,
    const float* __restrict__ Wy, const float* __restrict__ by,
    float* __restrict__ out)
{
    char* sm = smem_dyn;
    const uint32_t uBase = s2u(sm);

    const int tid  = threadIdx.x;
    const int w    = tid >> 5;
    const int lane = tid & 31;
    const int mt   = w >> 2;          // 0/1 -> rows mt*16..
    const int nt   = w & 3;           // j-subblock (4 cols)
    const int bid  = blockIdx.x;
    const int grp  = bid >> 4;        // 8 groups of 32 rows
    const int b0   = grp * 32;
    const int j0   = (bid & 15) * 16;
    unsigned* slots    = &g_slots[grp][0];
    unsigned* slotSelf = &g_slots[grp][bid & 15];

    // ---- stage W hi/lo once, gate-interleaved columns ----
    for (int i = tid; i < 64 * 256; i += 256) {
        int n = i & 63, k = i >> 6;
        int ntb = n >> 4, l = n & 15, g = l >> 2, q = l & 3;
        int j = j0 + ntb * 4 + q;
        const float* __restrict__ Wg = (g == 0) ? Wf : (g == 1) ? Wi : (g == 2) ? Wc : Wo;
        float v = Wg[(size_t)(DIN + k) * HID + j];
        int ck = k >> 5, kk = k & 31;
        uint32_t off = (uint32_t)(ck * 5120 + n * 80 + kk * 2);
        *(__nv_bfloat16*)(sm + S_WH + off) = __float2bfloat16(v);
        *(__nv_bfloat16*)(sm + S_WL + off) = __float2bfloat16(v - rebf(v));
    }

    // lane cell ownership (after shuffle exchange)
    const int gl   = lane >> 2;
    const int tg   = lane & 3;
    const bool lowhalf = (tg < 2);
    const int rowL = mt * 16 + gl + (lowhalf ? 0 : 8);
    const int rowG = b0 + rowL;
    const int jg   = j0 + nt * 4 + 2 * (tg & 1);
    const int len  = lengths[rowG];
    float2 cst = make_float2(0.f, 0.f);
    uint32_t hp0 = 0u, hp1 = 0u;

    // MMA fragment addressing
    const int arow  = lane & 15;
    const int ahalf = (lane >> 4) & 1;
    const int brow  = ((lane >> 4) & 1) * 8 + (lane & 7);
    const int bcol  = ((lane >> 3) & 1) * 8;

    // staging mapping
    const int srow = tid >> 3;
    const int sqd  = tid & 7;
    const uint32_t sOffBase = (uint32_t)(srow * 80 + sqd * 8);

    // prefetch xwb for t=0
    const float* xr0 = g_xwb + ((size_t)rowG) * 1024 + jg;
    float2 pf = __ldcg((const float2*)xr0);
    float2 pi = __ldcg((const float2*)(xr0 + 256));
    float2 pc = __ldcg((const float2*)(xr0 + 512));
    float2 po = __ldcg((const float2*)(xr0 + 768));

    for (int t = 0; t < TS; ++t) {
        const uint32_t* __restrict__ hprev = g_hpk[t & 1];
        uint32_t*       __restrict__ hnext = g_hpk[(t + 1) & 1];

        // ---- issue all 8 staging loads ----
        uint4 pA[8];
        {
            const uint32_t* hr = hprev + (size_t)(b0 + srow) * HID;
            #pragma unroll
            for (int it = 0; it < 8; ++it)
                pA[it] = __ldcg((const uint4*)(hr + (it * 8 + sqd) * 4));
        }

        // ---- store chunks 0..3 ----
        #pragma unroll
        for (int it = 0; it < 4; ++it) {
            uint4 p = pA[it];
            uint2 hi, lo;
            hi.x = __byte_perm(p.x, p.y, 0x7632);
            hi.y = __byte_perm(p.z, p.w, 0x7632);
            lo.x = __byte_perm(p.x, p.y, 0x5410);
            lo.y = __byte_perm(p.z, p.w, 0x5410);
            uint32_t off = (uint32_t)(it * 2560) + sOffBase;
            *(uint2*)(sm + S_AH + off) = hi;
            *(uint2*)(sm + S_AL + off) = lo;
        }
        __syncthreads();

        // ---- MMA chunks 0..3 ----
        float c0[4] = {0.f, 0.f, 0.f, 0.f};
        float c1[4] = {0.f, 0.f, 0.f, 0.f};
        #pragma unroll
        for (int ck = 0; ck < 4; ++ck) {
            #pragma unroll
            for (int ks = 0; ks < 2; ++ks) {
                const int kk = ks * 16;
                uint32_t ah[4], al[4], bh[4], bl[4];
                uint32_t ao = uBase + (uint32_t)(ck * 2560 + (mt * 16 + arow) * 80 + (kk + ahalf * 8) * 2);
                LDSM4(ah[0], ah[1], ah[2], ah[3], ao + S_AH);
                LDSM4(al[0], al[1], al[2], al[3], ao + S_AL);
                uint32_t bo = uBase + (uint32_t)(ck * 5120 + (nt * 16 + brow) * 80 + (kk + bcol) * 2);
                LDSM4(bh[0], bh[1], bh[2], bh[3], bo + S_WH);
                LDSM4(bl[0], bl[1], bl[2], bl[3], bo + S_WL);
                MMA16816(c0, ah, bh[0], bh[1]);
                MMA16816(c1, ah, bh[2], bh[3]);
                MMA16816(c0, ah, bl[0], bl[1]);
                MMA16816(c1, ah, bl[2], bl[3]);
                MMA16816(c0, al, bh[0], bh[1]);
                MMA16816(c1, al, bh[2], bh[3]);
            }
        }

        // ---- store chunks 4..7 ----
        #pragma unroll
        for (int it = 4; it < 8; ++it) {
            uint4 p = pA[it];
            uint2 hi, lo;
            hi.x = __byte_perm(p.x, p.y, 0x7632);
            hi.y = __byte_perm(p.z, p.w, 0x7632);
            lo.x = __byte_perm(p.x, p.y, 0x5410);
            lo.y = __byte_perm(p.z, p.w, 0x5410);
            uint32_t off = (uint32_t)(it * 2560) + sOffBase;
            *(uint2*)(sm + S_AH + off) = hi;
            *(uint2*)(sm + S_AL + off) = lo;
        }
        __syncthreads();

        // ---- MMA chunks 4..7 ----
        #pragma unroll
        for (int ck = 4; ck < 8; ++ck) {
            #pragma unroll
            for (int ks = 0; ks < 2; ++ks) {
                const int kk = ks * 16;
                uint32_t ah[4], al[4], bh[4], bl[4];
                uint32_t ao = uBase + (uint32_t)(ck * 2560 + (mt * 16 + arow) * 80 + (kk + ahalf * 8) * 2);
                LDSM4(ah[0], ah[1], ah[2], ah[3], ao + S_AH);
                LDSM4(al[0], al[1], al[2], al[3], ao + S_AL);
                uint32_t bo = uBase + (uint32_t)(ck * 5120 + (nt * 16 + brow) * 80 + (kk + bcol) * 2);
                LDSM4(bh[0], bh[1], bh[2], bh[3], bo + S_WH);
                LDSM4(bl[0], bl[1], bl[2], bl[3], bo + S_WL);
                MMA16816(c0, ah, bh[0], bh[1]);
                MMA16816(c1, ah, bh[2], bh[3]);
                MMA16816(c0, ah, bl[0], bl[1]);
                MMA16816(c1, ah, bl[2], bl[3]);
                MMA16816(c0, al, bh[0], bh[1]);
                MMA16816(c1, al, bh[2], bh[3]);
            }
        }

        // ---- warp-local gate exchange (shuffle xor 2) + epilogue ----
        {
            float s0 = lowhalf ? c0[2] : c0[0];
            float s1 = lowhalf ? c0[3] : c0[1];
            float s2 = lowhalf ? c1[2] : c1[0];
            float s3 = lowhalf ? c1[3] : c1[1];
            float e0 = __shfl_xor_sync(0xffffffffu, s0, 2);
            float e1 = __shfl_xor_sync(0xffffffffu, s1, 2);
            float e2 = __shfl_xor_sync(0xffffffffu, s2, 2);
            float e3 = __shfl_xor_sync(0xffffffffu, s3, 2);

            float f0, f1, i0, i1, q0, q1, o0, o1;
            if (lowhalf) {
                f0 = c0[0]; f1 = c0[1]; q0 = c1[0]; q1 = c1[1];
                i0 = e0;    i1 = e1;    o0 = e2;    o1 = e3;
            } else {
                i0 = c0[2]; i1 = c0[3]; o0 = c1[2]; o1 = c1[3];
                f0 = e0;    f1 = e1;    q0 = e2;    q1 = e3;
            }

            float fg0 = sigmoidf_(f0 + pf.x), fg1 = sigmoidf_(f1 + pf.y);
            float ig0 = sigmoidf_(i0 + pi.x), ig1 = sigmoidf_(i1 + pi.y);
            float ch0 = tanhf_(q0 + pc.x),    ch1 = tanhf_(q1 + pc.y);
            float og0 = sigmoidf_(o0 + po.x), og1 = sigmoidf_(o1 + po.y);
            float cn0 = fg0 * cst.x + ig0 * ch0;
            float cn1 = fg1 * cst.y + ig1 * ch1;
            float hn0 = og0 * tanhf_(cn0);
            float hn1 = og1 * tanhf_(cn1);
            if (t < len) {
                cst.x = cn0; cst.y = cn1;
                hp0 = packsplit(hn0); hp1 = packsplit(hn1);
            }
            uint2 hv; hv.x = hp0; hv.y = hp1;
            *(uint2*)(hnext + (size_t)rowG * HID + jg) = hv;
        }

        // ---- slot barrier: release own slot, prefetch next xwb, poll peers ----
        __syncthreads();                      // all publishes in CTA done
        const unsigned tgt = (unsigned)(t + 1);
        if (tid == 0)
            asm volatile("st.release.gpu.global.u32 [%0], %1;" :: "l"(slotSelf), "r"(tgt) : "memory");

        if (t + 1 < TS) {                     // hide DRAM latency under barrier wait
            const float* xr = g_xwb + ((size_t)(t + 1) * BSZ + rowG) * 1024 + jg;
            pf = __ldcg((const float2*)xr);
            pi = __ldcg((const float2*)(xr + 256));
            pc = __ldcg((const float2*)(xr + 512));
            po = __ldcg((const float2*)(xr + 768));
        }

        {   // every warp polls all 16 slots (lane -> slot), acquire loads
            unsigned v;
            do {
                asm volatile("ld.global.acquire.gpu.u32 %0, [%1];"
                             : "=r"(v) : "l"(slots + (lane & 15)));
            } while (__ballot_sync(0xffffffffu, v >= tgt) != 0xffffffffu);
        }
    }

    // global barrier before tail
    __syncthreads();
    if (tid == 0) {
        arrive_release(&g_bar);
        wait_target(&g_bar, (unsigned)NCTA_S);
    }
    __syncthreads();

    // tail: y = h @ Wy + by, then emit h (reconstructed fp32)
    const uint32_t* __restrict__ hfin = g_hpk[0];
    if (bid < 64) {
        const int row = bid * 4 + (tid >> 6);
        const int oc  = tid & 63;
        const uint32_t* hr = hfin + (size_t)row * HID;
        float acc = by[oc];
        #pragma unroll 4
        for (int k4 = 0; k4 < HID / 4; ++k4) {
            uint4 p = __ldcg((const uint4*)(hr + k4 * 4));
            const float* wp = Wy + (size_t)k4 * 4 * OUTD + oc;
            acc += unpacksplit(p.x) * wp[0] + unpacksplit(p.y) * wp[OUTD]
                 + unpacksplit(p.z) * wp[2 * OUTD] + unpacksplit(p.w) * wp[3 * OUTD];
        }
        out[(size_t)row * OUTD + oc] = acc;
    }
    {
        int idx = bid * 256 + tid;
        if (idx < BSZ * HID / 4) {
            uint4 p = __ldcg(((const uint4*)hfin) + idx);
            float4 v;
            v.x = unpacksplit(p.x); v.y = unpacksplit(p.y);
            v.z = unpacksplit(p.z); v.w = unpacksplit(p.w);
            ((float4*)(out + BSZ * OUTD))[idx] = v;
        }
    }
}

extern "C" void kernel_launch(void* const* d_in, const int* in_sizes, int n_in,
                              void* d_out, int out_size) {
    const float* x       = (const float*)d_in[0];
    const int*   lengths = (const int*)  d_in[1];
    const float* Wf = (const float*)d_in[2];  const float* bf = (const float*)d_in[3];
    const float* Wi = (const float*)d_in[4];  const float* bi = (const float*)d_in[5];
    const float* Wc = (const float*)d_in[6];  const float* bc = (const float*)d_in[7];
    const float* Wo = (const float*)d_in[8];  const float* bo = (const float*)d_in[9];
    const float* Wy = (const float*)d_in[10]; const float* by = (const float*)d_in[11];
    float* out = (float*)d_out;

    cudaFuncSetAttribute(xw_mma, cudaFuncAttributeMaxDynamicSharedMemorySize, SMEM_MMA);
    cudaFuncSetAttribute(lstm_serial, cudaFuncAttributeMaxDynamicSharedMemorySize, SMEM_SER);

    convert_x<<<(MROWS * DIN / 4) / 256, 256>>>(x);
    convert_w<<<1024, 256>>>(Wf, Wi, Wc, Wo);
    xw_mma<<<dim3(8, MROWS / 128), 256, SMEM_MMA>>>(bf, bi, bc, bo);
    init_state<<<64, 256>>>();
    lstm_serial<<<NCTA_S, 256, SMEM_SER>>>(lengths, Wf, Wi, Wc, Wo, Wy, by, out);
}

// round 14
// speedup vs baseline: 1.5946x; 1.5946x over previous
#include <cuda_runtime.h>
#include <cuda_bf16.h>
#include <cstdint>
#include <cstring>

#define TS   512
#define BSZ  256
#define DIN  256
#define HID  256
#define OUTD 64
#define MROWS (TS * BSZ)
#define NCTA_S 128           // serial: 8 row-groups x 16 col-CTAs
#define PAK  40              // staged tile pitch in bf16 (80B rows: ldmatrix conflict-free)

// xw_mma smem layout (bytes)
#define OFF_BIAS 0
#define OFF_AH   1024
#define OFF_AL   (OFF_AH + 128 * PAK * 2)
#define OFF_BH   (OFF_AL + 128 * PAK * 2)
#define OFF_BL   (OFF_BH + 128 * PAK * 2)
#define SMEM_MMA (OFF_BL + 128 * PAK * 2)      // 41984 B

// serial smem layout (bytes): A 32rx256k hi/lo, W 64nx256k hi/lo, pitch 80B, 8 k-chunks
#define S_AH  0
#define S_AL  20480            // 8 * 32*80
#define S_WH  40960
#define S_WL  (S_WH + 40960)
#define SMEM_SER (S_WL + 40960)   // 122880 B

extern __shared__ char smem_dyn[];

__device__ float          g_xwb[(size_t)MROWS * 1024];   // x@Wx + b, [m][g*256+j]
__device__ __nv_bfloat16  g_ah[(size_t)MROWS * DIN];
__device__ __nv_bfloat16  g_al[(size_t)MROWS * DIN];
__device__ __nv_bfloat16  g_wth[1024 * 256];              // W^T hi [n][k]
__device__ __nv_bfloat16  g_wtl[1024 * 256];              // W^T lo
__device__ uint32_t       g_hpk[2][BSZ * HID];            // h packed: hi bf16 <<16 | lo bf16
__device__ unsigned       g_rbar[16][64];                 // per-row-group barriers (256B apart)
__device__ unsigned       g_bar;                          // final global barrier

__device__ __forceinline__ float sigmoidf_(float x) { return 1.0f / (1.0f + __expf(-x)); }
__device__ __forceinline__ float tanhf_(float x) {
    float e = __expf(2.0f * x); return 1.0f - 2.0f / (e + 1.0f);
}
__device__ __forceinline__ uint32_t s2u(const void* p) {
    uint32_t a; asm("{ .reg .u64 t; cvta.to.shared.u64 t, %1; cvt.u32.u64 %0, t; }" : "=r"(a) : "l"(p));
    return a;
}
__device__ __forceinline__ uint32_t pack2(float a, float b) {
    __nv_bfloat162 t; t.x = __float2bfloat16(a); t.y = __float2bfloat16(b);
    uint32_t r; memcpy(&r, &t, 4); return r;
}
__device__ __forceinline__ float rebf(float v) {
    return __bfloat162float(__float2bfloat16(v));
}
__device__ __forceinline__ uint32_t packsplit(float v) {
    __nv_bfloat16 hb = __float2bfloat16(v);
    unsigned short hu; memcpy(&hu, &hb, 2);
    float hf = __uint_as_float((uint32_t)hu << 16);
    __nv_bfloat16 lb = __float2bfloat16(v - hf);
    unsigned short lu; memcpy(&lu, &lb, 2);
    return ((uint32_t)hu << 16) | (uint32_t)lu;
}
__device__ __forceinline__ float unpacksplit(uint32_t u) {
    return __uint_as_float(u & 0xFFFF0000u) + __uint_as_float(u << 16);
}
__device__ __forceinline__ void arrive_release(unsigned* ctr) {
    asm volatile("red.release.gpu.global.add.u32 [%0], %1;" :: "l"(ctr), "r"(1u) : "memory");
}
__device__ __forceinline__ void wait_target(const unsigned* ctr, unsigned tgt) {
    unsigned v;
    do {
        asm volatile("ld.global.acquire.gpu.u32 %0, [%1];" : "=r"(v) : "l"(ctr));
        if (v >= tgt) break;
        __nanosleep(20);
    } while (true);
}

#define LDSM4(d0, d1, d2, d3, addr) \
    asm volatile("ldmatrix.sync.aligned.m8n8.x4.shared.b16 {%0,%1,%2,%3}, [%4];" \
                 : "=r"(d0), "=r"(d1), "=r"(d2), "=r"(d3) : "r"(addr))

#define MMA16816(c, a, b0, b1) \
    asm volatile("mma.sync.aligned.m16n8k16.row.col.f32.bf16.bf16.f32 " \
                 "{%0,%1,%2,%3}, {%4,%5,%6,%7}, {%8,%9}, {%0,%1,%2,%3};" \
                 : "+f"((c)[0]), "+f"((c)[1]), "+f"((c)[2]), "+f"((c)[3]) \
                 : "r"((a)[0]), "r"((a)[1]), "r"((a)[2]), "r"((a)[3]), "r"(b0), "r"(b1))

// ---------------- conversions ----------------
__global__ void convert_x(const float* __restrict__ x) {
    size_t i = (size_t)blockIdx.x * 256 + threadIdx.x;
    float4 v = ((const float4*)x)[i];
    uint2 ph, pl;
    ph.x = pack2(v.x, v.y); ph.y = pack2(v.z, v.w);
    pl.x = pack2(v.x - rebf(v.x), v.y - rebf(v.y));
    pl.y = pack2(v.z - rebf(v.z), v.w - rebf(v.w));
    ((uint2*)g_ah)[i] = ph;
    ((uint2*)g_al)[i] = pl;
}

__global__ void convert_w(const float* __restrict__ Wf, const float* __restrict__ Wi,
                          const float* __restrict__ Wc, const float* __restrict__ Wo) {
    int n = blockIdx.x, k = threadIdx.x;
    int g = n >> 8, j = n & 255;
    const float* Wg = (g == 0) ? Wf : (g == 1) ? Wi : (g == 2) ? Wc : Wo;
    float v = Wg[(size_t)k * HID + j];
    g_wth[n * 256 + k] = __float2bfloat16(v);
    g_wtl[n * 256 + k] = __float2bfloat16(v - rebf(v));
}

// ---------------- xwb = x @ Wx + b via mma.sync bf16 3-term split ----------------
__global__ void __launch_bounds__(256) xw_mma(
    const float* __restrict__ bfp, const float* __restrict__ bip,
    const float* __restrict__ bcp, const float* __restrict__ bop)
{
    char* sm = smem_dyn;
    float* sBias = (float*)(sm + OFF_BIAS);
    const uint32_t uAh = s2u(sm + OFF_AH);
    const uint32_t uAl = s2u(sm + OFF_AL);
    const uint32_t uBh = s2u(sm + OFF_BH);
    const uint32_t uBl = s2u(sm + OFF_BL);

    const int tid  = threadIdx.x;
    const int w    = tid >> 5;
    const int lane = tid & 31;
    const int wm   = w & 3;
    const int wn   = w >> 2;
    const int n0   = blockIdx.x * 128;
    const int m0   = blockIdx.y * 128;

    if (tid < 128) {
        int g = n0 >> 8;
        const float* bg = (g == 0) ? bfp : (g == 1) ? bip : (g == 2) ? bcp : bop;
        sBias[tid] = bg[(n0 & 255) + tid];
    }

    const int arow  = lane & 15;
    const int ahalf = (lane >> 4) & 1;
    const int brow  = ((lane >> 4) & 1) * 8 + (lane & 7);
    const int bcol  = ((lane >> 3) & 1) * 8;

    float c[2][8][4];
    #pragma unroll
    for (int mt = 0; mt < 2; ++mt)
        #pragma unroll
        for (int nt = 0; nt < 8; ++nt)
            #pragma unroll
            for (int q = 0; q < 4; ++q) c[mt][nt][q] = 0.f;

    for (int ck = 0; ck < 8; ++ck) {
        const int k0 = ck * 32;
        __syncthreads();
        #pragma unroll
        for (int it = 0; it < 2; ++it) {
            int idx = tid + it * 256;
            int r = idx >> 2, cq = idx & 3;
            uint32_t doff = (uint32_t)(r * (PAK * 2) + cq * 16);
            *(uint4*)(sm + OFF_AH + doff) = *(const uint4*)(g_ah  + (size_t)(m0 + r) * 256 + k0 + cq * 8);
            *(uint4*)(sm + OFF_AL + doff) = *(const uint4*)(g_al  + (size_t)(m0 + r) * 256 + k0 + cq * 8);
            *(uint4*)(sm + OFF_BH + doff) = *(const uint4*)(g_wth + (size_t)(n0 + r) * 256 + k0 + cq * 8);
            *(uint4*)(sm + OFF_BL + doff) = *(const uint4*)(g_wtl + (size_t)(n0 + r) * 256 + k0 + cq * 8);
        }
        __syncthreads();

        #pragma unroll
        for (int ks = 0; ks < 2; ++ks) {
            const int kk = ks * 16;
            uint32_t ah[2][4], al[2][4];
            #pragma unroll
            for (int mt = 0; mt < 2; ++mt) {
                uint32_t ao = (uint32_t)((wm * 32 + mt * 16 + arow) * (PAK * 2) + (kk + ahalf * 8) * 2);
                LDSM4(ah[mt][0], ah[mt][1], ah[mt][2], ah[mt][3], uAh + ao);
                LDSM4(al[mt][0], al[mt][1], al[mt][2], al[mt][3], uAl + ao);
            }
            #pragma unroll
            for (int np = 0; np < 4; ++np) {
                uint32_t bo = (uint32_t)((wn * 64 + np * 16 + brow) * (PAK * 2) + (kk + bcol) * 2);
                uint32_t bh[4], bl[4];
                LDSM4(bh[0], bh[1], bh[2], bh[3], uBh + bo);
                LDSM4(bl[0], bl[1], bl[2], bl[3], uBl + bo);
                #pragma unroll
                for (int mt = 0; mt < 2; ++mt) {
                    MMA16816(c[mt][2 * np],     ah[mt], bh[0], bh[1]);
                    MMA16816(c[mt][2 * np + 1], ah[mt], bh[2], bh[3]);
                    MMA16816(c[mt][2 * np],     ah[mt], bl[0], bl[1]);
                    MMA16816(c[mt][2 * np + 1], ah[mt], bl[2], bl[3]);
                    MMA16816(c[mt][2 * np],     al[mt], bh[0], bh[1]);
                    MMA16816(c[mt][2 * np + 1], al[mt], bh[2], bh[3]);
                }
            }
        }
    }

    const int g  = lane >> 2;
    const int tg = lane & 3;
    float* base = g_xwb + (size_t)(m0 + wm * 32) * 1024 + n0 + wn * 64;
    #pragma unroll
    for (int mt = 0; mt < 2; ++mt) {
        #pragma unroll
        for (int nt = 0; nt < 8; ++nt) {
            float2 bv = *(float2*)&sBias[wn * 64 + nt * 8 + 2 * tg];
            float2 v0, v1;
            v0.x = c[mt][nt][0] + bv.x; v0.y = c[mt][nt][1] + bv.y;
            v1.x = c[mt][nt][2] + bv.x; v1.y = c[mt][nt][3] + bv.y;
            *(float2*)(base + (size_t)(mt * 16 + g)     * 1024 + nt * 8 + 2 * tg) = v0;
            *(float2*)(base + (size_t)(mt * 16 + g + 8) * 1024 + nt * 8 + 2 * tg) = v1;
        }
    }
}

// ---------------- init ----------------
__global__ void init_state() {
    int i = blockIdx.x * blockDim.x + threadIdx.x;
    if (i == 0) g_bar = 0u;
    if (i < 16 * 64) ((unsigned*)g_rbar)[i] = 0u;
    if (i < BSZ * HID / 4) ((uint4*)g_hpk[0])[i] = make_uint4(0u, 0u, 0u, 0u);
}

// ---------------- serial loop: h @ Wh via mma.sync, warp-local epilogue ----------------
// 128 CTAs = 8 row-groups(32 rows) x 16 col-CTAs(16 hcols).
// R12 structure (atomic group barrier, single-thread nanosleep poll) with the
// next-step xwb prefetch hoisted BEFORE the barrier wait (hides DRAM latency).
__global__ void __launch_bounds__(256, 1) lstm_serial(
    const int* __restrict__ lengths,
    const float* __restrict__ Wf, const float* __restrict__ Wi,
    const float* __restrict__ Wc, const float* __restrict__ Wo,
    const float* __restrict__ Wy, const float* __restrict__ by,
    float* __restrict__ out)
{
    char* sm = smem_dyn;
    const uint32_t uBase = s2u(sm);

    const int tid  = threadIdx.x;
    const int w    = tid >> 5;
    const int lane = tid & 31;
    const int mt   = w >> 2;          // 0/1 -> rows mt*16..
    const int nt   = w & 3;           // j-subblock (4 cols)
    const int bid  = blockIdx.x;
    const int grp  = bid >> 4;        // 8 groups of 32 rows
    const int b0   = grp * 32;
    const int j0   = (bid & 15) * 16;
    unsigned* myctr = &g_rbar[grp][0];

    // ---- stage W hi/lo once, gate-interleaved columns ----
    for (int i = tid; i < 64 * 256; i += 256) {
        int n = i & 63, k = i >> 6;
        int ntb = n >> 4, l = n & 15, g = l >> 2, q = l & 3;
        int j = j0 + ntb * 4 + q;
        const float* __restrict__ Wg = (g == 0) ? Wf : (g == 1) ? Wi : (g == 2) ? Wc : Wo;
        float v = Wg[(size_t)(DIN + k) * HID + j];
        int ck = k >> 5, kk = k & 31;
        uint32_t off = (uint32_t)(ck * 5120 + n * 80 + kk * 2);
        *(__nv_bfloat16*)(sm + S_WH + off) = __float2bfloat16(v);
        *(__nv_bfloat16*)(sm + S_WL + off) = __float2bfloat16(v - rebf(v));
    }

    // lane cell ownership (after shuffle exchange)
    const int gl   = lane >> 2;
    const int tg   = lane & 3;
    const bool lowhalf = (tg < 2);
    const int rowL = mt * 16 + gl + (lowhalf ? 0 : 8);
    const int rowG = b0 + rowL;
    const int jg   = j0 + nt * 4 + 2 * (tg & 1);
    const int len  = lengths[rowG];
    float2 cst = make_float2(0.f, 0.f);
    uint32_t hp0 = 0u, hp1 = 0u;

    // MMA fragment addressing
    const int arow  = lane & 15;
    const int ahalf = (lane >> 4) & 1;
    const int brow  = ((lane >> 4) & 1) * 8 + (lane & 7);
    const int bcol  = ((lane >> 3) & 1) * 8;

    // staging mapping
    const int srow = tid >> 3;
    const int sqd  = tid & 7;
    const uint32_t sOffBase = (uint32_t)(srow * 80 + sqd * 8);

    // prefetch xwb for t=0
    const float* xr0 = g_xwb + ((size_t)rowG) * 1024 + jg;
    float2 pf = __ldcg((const float2*)xr0);
    float2 pi = __ldcg((const float2*)(xr0 + 256));
    float2 pc = __ldcg((const float2*)(xr0 + 512));
    float2 po = __ldcg((const float2*)(xr0 + 768));

    for (int t = 0; t < TS; ++t) {
        const uint32_t* __restrict__ hprev = g_hpk[t & 1];
        uint32_t*       __restrict__ hnext = g_hpk[(t + 1) & 1];

        // ---- issue all 8 staging loads ----
        uint4 pA[8];
        {
            const uint32_t* hr = hprev + (size_t)(b0 + srow) * HID;
            #pragma unroll
            for (int it = 0; it < 8; ++it)
                pA[it] = __ldcg((const uint4*)(hr + (it * 8 + sqd) * 4));
        }

        // ---- store chunks 0..3 ----
        #pragma unroll
        for (int it = 0; it < 4; ++it) {
            uint4 p = pA[it];
            uint2 hi, lo;
            hi.x = __byte_perm(p.x, p.y, 0x7632);
            hi.y = __byte_perm(p.z, p.w, 0x7632);
            lo.x = __byte_perm(p.x, p.y, 0x5410);
            lo.y = __byte_perm(p.z, p.w, 0x5410);
            uint32_t off = (uint32_t)(it * 2560) + sOffBase;
            *(uint2*)(sm + S_AH + off) = hi;
            *(uint2*)(sm + S_AL + off) = lo;
        }
        __syncthreads();

        // ---- MMA chunks 0..3 ----
        float c0[4] = {0.f, 0.f, 0.f, 0.f};
        float c1[4] = {0.f, 0.f, 0.f, 0.f};
        #pragma unroll
        for (int ck = 0; ck < 4; ++ck) {
            #pragma unroll
            for (int ks = 0; ks < 2; ++ks) {
                const int kk = ks * 16;
                uint32_t ah[4], al[4], bh[4], bl[4];
                uint32_t ao = uBase + (uint32_t)(ck * 2560 + (mt * 16 + arow) * 80 + (kk + ahalf * 8) * 2);
                LDSM4(ah[0], ah[1], ah[2], ah[3], ao + S_AH);
                LDSM4(al[0], al[1], al[2], al[3], ao + S_AL);
                uint32_t bo = uBase + (uint32_t)(ck * 5120 + (nt * 16 + brow) * 80 + (kk + bcol) * 2);
                LDSM4(bh[0], bh[1], bh[2], bh[3], bo + S_WH);
                LDSM4(bl[0], bl[1], bl[2], bl[3], bo + S_WL);
                MMA16816(c0, ah, bh[0], bh[1]);
                MMA16816(c1, ah, bh[2], bh[3]);
                MMA16816(c0, ah, bl[0], bl[1]);
                MMA16816(c1, ah, bl[2], bl[3]);
                MMA16816(c0, al, bh[0], bh[1]);
                MMA16816(c1, al, bh[2], bh[3]);
            }
        }

        // ---- store chunks 4..7 ----
        #pragma unroll
        for (int it = 4; it < 8; ++it) {
            uint4 p = pA[it];
            uint2 hi, lo;
            hi.x = __byte_perm(p.x, p.y, 0x7632);
            hi.y = __byte_perm(p.z, p.w, 0x7632);
            lo.x = __byte_perm(p.x, p.y, 0x5410);
            lo.y = __byte_perm(p.z, p.w, 0x5410);
            uint32_t off = (uint32_t)(it * 2560) + sOffBase;
            *(uint2*)(sm + S_AH + off) = hi;
            *(uint2*)(sm + S_AL + off) = lo;
        }
        __syncthreads();

        // ---- MMA chunks 4..7 ----
        #pragma unroll
        for (int ck = 4; ck < 8; ++ck) {
            #pragma unroll
            for (int ks = 0; ks < 2; ++ks) {
                const int kk = ks * 16;
                uint32_t ah[4], al[4], bh[4], bl[4];
                uint32_t ao = uBase + (uint32_t)(ck * 2560 + (mt * 16 + arow) * 80 + (kk + ahalf * 8) * 2);
                LDSM4(ah[0], ah[1], ah[2], ah[3], ao + S_AH);
                LDSM4(al[0], al[1], al[2], al[3], ao + S_AL);
                uint32_t bo = uBase + (uint32_t)(ck * 5120 + (nt * 16 + brow) * 80 + (kk + bcol) * 2);
                LDSM4(bh[0], bh[1], bh[2], bh[3], bo + S_WH);
                LDSM4(bl[0], bl[1], bl[2], bl[3], bo + S_WL);
                MMA16816(c0, ah, bh[0], bh[1]);
                MMA16816(c1, ah, bh[2], bh[3]);
                MMA16816(c0, ah, bl[0], bl[1]);
                MMA16816(c1, ah, bl[2], bl[3]);
                MMA16816(c0, al, bh[0], bh[1]);
                MMA16816(c1, al, bh[2], bh[3]);
            }
        }

        // ---- warp-local gate exchange (shuffle xor 2) + epilogue ----
        {
            float s0 = lowhalf ? c0[2] : c0[0];
            float s1 = lowhalf ? c0[3] : c0[1];
            float s2 = lowhalf ? c1[2] : c1[0];
            float s3 = lowhalf ? c1[3] : c1[1];
            float e0 = __shfl_xor_sync(0xffffffffu, s0, 2);
            float e1 = __shfl_xor_sync(0xffffffffu, s1, 2);
            float e2 = __shfl_xor_sync(0xffffffffu, s2, 2);
            float e3 = __shfl_xor_sync(0xffffffffu, s3, 2);

            float f0, f1, i0, i1, q0, q1, o0, o1;
            if (lowhalf) {
                f0 = c0[0]; f1 = c0[1]; q0 = c1[0]; q1 = c1[1];
                i0 = e0;    i1 = e1;    o0 = e2;    o1 = e3;
            } else {
                i0 = c0[2]; i1 = c0[3]; o0 = c1[2]; o1 = c1[3];
                f0 = e0;    f1 = e1;    q0 = e2;    q1 = e3;
            }

            float fg0 = sigmoidf_(f0 + pf.x), fg1 = sigmoidf_(f1 + pf.y);
            float ig0 = sigmoidf_(i0 + pi.x), ig1 = sigmoidf_(i1 + pi.y);
            float ch0 = tanhf_(q0 + pc.x),    ch1 = tanhf_(q1 + pc.y);
            float og0 = sigmoidf_(o0 + po.x), og1 = sigmoidf_(o1 + po.y);
            float cn0 = fg0 * cst.x + ig0 * ch0;
            float cn1 = fg1 * cst.y + ig1 * ch1;
            float hn0 = og0 * tanhf_(cn0);
            float hn1 = og1 * tanhf_(cn1);
            if (t < len) {
                cst.x = cn0; cst.y = cn1;
                hp0 = packsplit(hn0); hp1 = packsplit(hn1);
            }
            uint2 hv; hv.x = hp0; hv.y = hp1;
            *(uint2*)(hnext + (size_t)rowG * HID + jg) = hv;
        }

        // ---- prefetch next-step xwb BEFORE barrier (hidden under wait) ----
        if (t + 1 < TS) {
            const float* xr = g_xwb + ((size_t)(t + 1) * BSZ + rowG) * 1024 + jg;
            pf = __ldcg((const float2*)xr);
            pi = __ldcg((const float2*)(xr + 256));
            pc = __ldcg((const float2*)(xr + 512));
            po = __ldcg((const float2*)(xr + 768));
        }

        // ---- row-group barrier (16 arrivals), R12-style single-thread poll ----
        __syncthreads();
        if (tid == 0) {
            arrive_release(myctr);
            wait_target(myctr, 16u * (unsigned)(t + 1));
        }
        __syncthreads();
    }

    // global barrier before tail
    if (tid == 0) {
        arrive_release(&g_bar);
        wait_target(&g_bar, (unsigned)NCTA_S);
    }
    __syncthreads();

    // tail: y = h @ Wy + by, then emit h (reconstructed fp32)
    const uint32_t* __restrict__ hfin = g_hpk[0];
    if (bid < 64) {
        const int row = bid * 4 + (tid >> 6);
        const int oc  = tid & 63;
        const uint32_t* hr = hfin + (size_t)row * HID;
        float acc = by[oc];
        #pragma unroll 4
        for (int k4 = 0; k4 < HID / 4; ++k4) {
            uint4 p = __ldcg((const uint4*)(hr + k4 * 4));
            const float* wp = Wy + (size_t)k4 * 4 * OUTD + oc;
            acc += unpacksplit(p.x) * wp[0] + unpacksplit(p.y) * wp[OUTD]
                 + unpacksplit(p.z) * wp[2 * OUTD] + unpacksplit(p.w) * wp[3 * OUTD];
        }
        out[(size_t)row * OUTD + oc] = acc;
    }
    {
        int idx = bid * 256 + tid;
        if (idx < BSZ * HID / 4) {
            uint4 p = __ldcg(((const uint4*)hfin) + idx);
            float4 v;
            v.x = unpacksplit(p.x); v.y = unpacksplit(p.y);
            v.z = unpacksplit(p.z); v.w = unpacksplit(p.w);
            ((float4*)(out + BSZ * OUTD))[idx] = v;
        }
    }
}

extern "C" void kernel_launch(void* const* d_in, const int* in_sizes, int n_in,
                              void* d_out, int out_size) {
    const float* x       = (const float*)d_in[0];
    const int*   lengths = (const int*)  d_in[1];
    const float* Wf = (const float*)d_in[2];  const float* bf = (const float*)d_in[3];
    const float* Wi = (const float*)d_in[4];  const float* bi = (const float*)d_in[5];
    const float* Wc = (const float*)d_in[6];  const float* bc = (const float*)d_in[7];
    const float* Wo = (const float*)d_in[8];  const float* bo = (const float*)d_in[9];
    const float* Wy = (const float*)d_in[10]; const float* by = (const float*)d_in[11];
    float* out = (float*)d_out;

    cudaFuncSetAttribute(xw_mma, cudaFuncAttributeMaxDynamicSharedMemorySize, SMEM_MMA);
    cudaFuncSetAttribute(lstm_serial, cudaFuncAttributeMaxDynamicSharedMemorySize, SMEM_SER);

    convert_x<<<(MROWS * DIN / 4) / 256, 256>>>(x);
    convert_w<<<1024, 256>>>(Wf, Wi, Wc, Wo);
    xw_mma<<<dim3(8, MROWS / 128), 256, SMEM_MMA>>>(bf, bi, bc, bo);
    init_state<<<64, 256>>>();
    lstm_serial<<<NCTA_S, 256, SMEM_SER>>>(lengths, Wf, Wi, Wc, Wo, Wy, by, out);
}